// round 11
// baseline (speedup 1.0000x reference)
#include <cuda_runtime.h>

// LIF recurrence: v = alpha*v + beta*c; spike = (v >= 1); v = spike ? 0 : v.
//
// R10: R7's exact config (1024 x 32 threads, 4-slot x U=16 register ring)
// plus L2 prefetch 8 phases ahead. Evidence: R4/R7/R8 all pinned at 74-75%
// DRAM regardless of register-ring depth (4->6MB in flight) or SMSP spread;
// read concurrency is capped by what registers can hold. prefetch.global.L2
// decouples the DRAM read stream from the register budget: prefetches stream
// currents into L2 ~128 steps early (chip-wide ~16MB window << 126MB L2),
// ring refill LDGs then hit L2 (~250cyc, covered 4x by the 4-phase ring).

// Bit-identical arithmetic to the reference:
// ALPHA = float(np.exp(-1/20)), BETA = float(1 - ALPHA_double).
#define ALPHA_F ((float)0.95122942450071400910)
#define BETA_F  ((float)0.04877057549928599090)

__device__ __forceinline__ void l2_prefetch(const float* p)
{
    asm volatile("prefetch.global.L2 [%0];" :: "l"(p));
}

template<int T, int N, int U>
__global__ void __launch_bounds__(32)
lif_pf(const float* __restrict__ cur, const float* __restrict__ v0,
       float* __restrict__ spikes, float* __restrict__ volts)
{
    const int n = blockIdx.x * blockDim.x + threadIdx.x;   // one thread per neuron
    float v = v0[n];

    const float* P0 = cur    + n;
    float*       ps = spikes + n;
    float*       pv = volts  + n;

    static_assert(T % U == 0 && (T / U) % 4 == 0, "phase count must divide by 4");
    constexpr int ITERS = T / U;   // 128 phases for T=2048, U=16

    float buf[4][U];

    // Prologue: ring loads for phases 0..3 (DRAM, latency eaten once),
    // then L2 prefetches for phases 4..11.
#pragma unroll
    for (int k = 0; k < 4; ++k)
#pragma unroll
        for (int u = 0; u < U; ++u)
            buf[k][u] = __ldcs(P0 + (size_t)(k * U + u) * N);

#pragma unroll
    for (int j = 4; j < 12; ++j)
#pragma unroll
        for (int u = 0; u < U; ++u)
            l2_prefetch(P0 + (size_t)(j * U + u) * N);

    const float* p = P0 + (size_t)4 * U * N;   // refill pointer (phase 4)

    // Main loop over phase groups. While computing phase i+k:
    //   refill ring slot k with phase i+k+4  (L2 hit thanks to prefetch)
    //   L2-prefetch phase i+k+8             (arrives ~4 phases before its LDG)
    for (int i = 0; i < ITERS - 4; i += 4) {
#pragma unroll
        for (int k = 0; k < 4; ++k) {
#pragma unroll
            for (int u = 0; u < U; ++u) {
                v = fmaf(ALPHA_F, v, BETA_F * buf[k][u]);
                const bool sp = (v >= 1.0f);
                __stcs(ps + (size_t)u * N, sp ? 1.0f : 0.0f);
                v = sp ? 0.0f : v;                 // V_RESET = 0
                __stcs(pv + (size_t)u * N, v);
            }
            ps += (size_t)U * N;  pv += (size_t)U * N;

            // Refill slot k from phase i+k+4 (should be L2-resident).
#pragma unroll
            for (int u = 0; u < U; ++u)
                buf[k][u] = __ldcs(p + (size_t)u * N);

            // Prefetch phase i+k+8 into L2 (guard the tail).
            if (i + k + 8 < ITERS) {
#pragma unroll
                for (int u = 0; u < U; ++u)
                    l2_prefetch(p + (size_t)(4 * U + u) * N);
            }
            p += (size_t)U * N;
        }
    }

    // Epilogue: last 4 phases from the ring, no refills.
#pragma unroll
    for (int k = 0; k < 4; ++k) {
#pragma unroll
        for (int u = 0; u < U; ++u) {
            v = fmaf(ALPHA_F, v, BETA_F * buf[k][u]);
            const bool sp = (v >= 1.0f);
            __stcs(ps + (size_t)u * N, sp ? 1.0f : 0.0f);
            v = sp ? 0.0f : v;
            __stcs(pv + (size_t)u * N, v);
        }
        ps += (size_t)U * N;  pv += (size_t)U * N;
    }
}

// Generic fallback (any T, N).
__global__ void lif_generic(const float* __restrict__ cur, const float* __restrict__ v0,
                            float* __restrict__ spikes, float* __restrict__ volts,
                            int T, int N)
{
    int n = blockIdx.x * blockDim.x + threadIdx.x;
    if (n >= N) return;
    float v = v0[n];
    size_t idx = (size_t)n;
    for (int t = 0; t < T; ++t) {
        float c = __ldcs(cur + idx);
        v = fmaf(ALPHA_F, v, BETA_F * c);
        const bool sp = (v >= 1.0f);
        __stcs(spikes + idx, sp ? 1.0f : 0.0f);
        v = sp ? 0.0f : v;
        __stcs(volts + idx, v);
        idx += (size_t)N;
    }
}

extern "C" void kernel_launch(void* const* d_in, const int* in_sizes, int n_in,
                              void* d_out, int out_size)
{
    // metadata order: currents (T*N), v0 (N)
    const float* cur = (const float*)d_in[0];
    const float* v0  = (const float*)d_in[1];

    const int N = in_sizes[1];
    const int T = in_sizes[0] / N;

    float* out    = (float*)d_out;
    float* spikes = out;                          // first T*N elements
    float* volts  = out + (size_t)T * (size_t)N;  // second T*N elements

    if (T == 2048 && N == 32768) {
        // R7's proven launch shape: 1024 blocks x 32 threads, single wave.
        lif_pf<2048, 32768, 16><<<1024, 32>>>(cur, v0, spikes, volts);
    } else {
        const int threads = 128;
        lif_generic<<<(N + threads - 1) / threads, threads>>>(cur, v0, spikes, volts, T, N);
    }
}

// round 14
// speedup vs baseline: 1.0753x; 1.0753x over previous
#include <cuda_runtime.h>

// LIF recurrence: v = alpha*v + beta*c; spike = (v >= 1); v = spike ? 0 : v.
//
// R11: best-known config (R7: 1024 blocks x 32 threads, 4-slot x U=16 ring),
// with refill loads interleaved per-element into the compute loop instead of
// issued as a burst after it. Five configs all pinned at 72-75% DRAM
// (~6 TB/s): per-warp MLP is at the ~55-line cap, warp count is fixed by
// N=32768, and the limiter is the mixed 1R:2W DRAM ceiling. The remaining
// lever is duty smoothing: keep LDG issue continuous through each phase
// (each element's refill still lands ~4 phases / >1500 cyc before its use).

// Bit-identical arithmetic to the reference:
// ALPHA = float(np.exp(-1/20)), BETA = float(1 - ALPHA_double).
#define ALPHA_F ((float)0.95122942450071400910)
#define BETA_F  ((float)0.04877057549928599090)

template<int T, int N, int U>
__global__ void __launch_bounds__(32)
lif_il(const float* __restrict__ cur, const float* __restrict__ v0,
       float* __restrict__ spikes, float* __restrict__ volts)
{
    const int n = blockIdx.x * blockDim.x + threadIdx.x;   // one thread per neuron
    float v = v0[n];

    const float* p  = cur    + n;
    float*       ps = spikes + n;
    float*       pv = volts  + n;

    static_assert(T % U == 0 && (T / U) % 4 == 0, "phase count must divide by 4");
    constexpr int ITERS = T / U;   // 128 phases for T=2048, U=16

    float buf[4][U];

    // Prologue: fill all 4 ring slots (phases 0..3).
#pragma unroll
    for (int k = 0; k < 4; ++k)
#pragma unroll
        for (int u = 0; u < U; ++u)
            buf[k][u] = __ldcs(p + (size_t)(k * U + u) * N);
    p += (size_t)4 * U * N;        // refill pointer = phase 4

    // Main loop: for each phase, consume element u and immediately issue its
    // phase+4 refill -> loads issue continuously, never in a burst.
    for (int i = 0; i < ITERS - 4; i += 4) {
#pragma unroll
        for (int k = 0; k < 4; ++k) {
#pragma unroll
            for (int u = 0; u < U; ++u) {
                const float c = buf[k][u];
                buf[k][u] = __ldcs(p + (size_t)u * N);   // refill (used 4 phases later)
                v = fmaf(ALPHA_F, v, BETA_F * c);
                const bool sp = (v >= 1.0f);
                __stcs(ps + (size_t)u * N, sp ? 1.0f : 0.0f);
                v = sp ? 0.0f : v;                        // V_RESET = 0
                __stcs(pv + (size_t)u * N, v);
            }
            ps += (size_t)U * N;  pv += (size_t)U * N;  p += (size_t)U * N;
        }
    }

    // Epilogue: last 4 phases, no refills.
#pragma unroll
    for (int k = 0; k < 4; ++k) {
#pragma unroll
        for (int u = 0; u < U; ++u) {
            v = fmaf(ALPHA_F, v, BETA_F * buf[k][u]);
            const bool sp = (v >= 1.0f);
            __stcs(ps + (size_t)u * N, sp ? 1.0f : 0.0f);
            v = sp ? 0.0f : v;
            __stcs(pv + (size_t)u * N, v);
        }
        ps += (size_t)U * N;  pv += (size_t)U * N;
    }
}

// Generic fallback (any T, N).
__global__ void lif_generic(const float* __restrict__ cur, const float* __restrict__ v0,
                            float* __restrict__ spikes, float* __restrict__ volts,
                            int T, int N)
{
    int n = blockIdx.x * blockDim.x + threadIdx.x;
    if (n >= N) return;
    float v = v0[n];
    size_t idx = (size_t)n;
    for (int t = 0; t < T; ++t) {
        float c = __ldcs(cur + idx);
        v = fmaf(ALPHA_F, v, BETA_F * c);
        const bool sp = (v >= 1.0f);
        __stcs(spikes + idx, sp ? 1.0f : 0.0f);
        v = sp ? 0.0f : v;
        __stcs(volts + idx, v);
        idx += (size_t)N;
    }
}

extern "C" void kernel_launch(void* const* d_in, const int* in_sizes, int n_in,
                              void* d_out, int out_size)
{
    // metadata order: currents (T*N), v0 (N)
    const float* cur = (const float*)d_in[0];
    const float* v0  = (const float*)d_in[1];

    const int N = in_sizes[1];
    const int T = in_sizes[0] / N;

    float* out    = (float*)d_out;
    float* spikes = out;                          // first T*N elements
    float* volts  = out + (size_t)T * (size_t)N;  // second T*N elements

    if (T == 2048 && N == 32768) {
        // Proven launch shape: 1024 blocks x 32 threads (1024 warps, single wave).
        lif_il<2048, 32768, 16><<<1024, 32>>>(cur, v0, spikes, volts);
    } else {
        const int threads = 128;
        lif_generic<<<(N + threads - 1) / threads, threads>>>(cur, v0, spikes, volts, T, N);
    }
}